// round 16
// baseline (speedup 1.0000x reference)
#include <cuda_runtime.h>
#include <cstdint>
#include <cfloat>

#define Sdim 512
#define Bdim 64
#define Hdim 1024
#define EHdim 1024
#define Vdim 50257
#define Ktot 2048              // H + EH
#define NTILE 8                // s-tiles per b
#define TS    64               // s per tile
#define SUBS  16               // s per online sub-tile
#define LSP_CH 4               // logsoftmax partial chunks per row
#define LSP_SEG 8              // subtract segments per row

// ---- scratch (no allocations allowed) ----
__device__ float g_h[Bdim * Hdim];
__device__ float g_u[Bdim * EHdim];
__device__ float g_scores[Bdim * Sdim];
__device__ float g_mt[Bdim * NTILE];
__device__ float g_lt[Bdim * NTILE];
__device__ float g_pctx[Bdim * NTILE * EHdim];   // 2 MB partial contexts
__device__ float g_y[Bdim * Ktot];   // [h | context], K-major per b
__device__ float g_lsm[Bdim * LSP_CH];
__device__ float g_lss[Bdim * LSP_CH];

// ============================================================================
// sm_80-class PTX helpers (safe under .target sm_103 — no 'a' features)
// ============================================================================
__device__ __forceinline__ uint32_t smem_to_u32(const void* p) {
    uint32_t a;
    asm("{ .reg .u64 t; cvta.to.shared.u64 t, %1; cvt.u32.u64 %0, t; }" : "=r"(a) : "l"(p));
    return a;
}
__device__ __forceinline__ void cp_async16(uint32_t dst, const void* src) {
    asm volatile("cp.async.ca.shared.global [%0], [%1], 16;" :: "r"(dst), "l"(src));
}
__device__ __forceinline__ void cp_async16_zfill(uint32_t dst, const void* src, int src_bytes) {
    asm volatile("cp.async.ca.shared.global [%0], [%1], 16, %2;"
                 :: "r"(dst), "l"(src), "r"(src_bytes));
}
#define CP_COMMIT() asm volatile("cp.async.commit_group;" ::: "memory")
#define CP_WAIT(n)  asm volatile("cp.async.wait_group %0;" :: "n"(n) : "memory")

__device__ __forceinline__ void mma_tf32(float* c, const uint32_t* a, const uint32_t* b) {
    asm volatile("mma.sync.aligned.m16n8k8.row.col.f32.tf32.tf32.f32 "
        "{%0,%1,%2,%3}, {%4,%5,%6,%7}, {%8,%9}, {%0,%1,%2,%3};"
        : "+f"(c[0]), "+f"(c[1]), "+f"(c[2]), "+f"(c[3])
        : "r"(a[0]), "r"(a[1]), "r"(a[2]), "r"(a[3]), "r"(b[0]), "r"(b[1]));
}

// ---------------------------------------------------------------------------
// K1: GRU with h0=0 => gh = b_hh. Tiled GEMM: block = 8 j x 64 b, K via smem.
// ---------------------------------------------------------------------------
__global__ __launch_bounds__(256) void gru_kernel(
    const float* __restrict__ x, const float* __restrict__ W_ih,
    const float* __restrict__ b_ih, const float* __restrict__ b_hh,
    float* __restrict__ out_h)
{
    __shared__ float w_s[24][33];
    __shared__ float x_s[32][65];

    const int t  = threadIdx.x;
    const int j0 = blockIdx.x * 8;
    const int jj = t & 7;
    const int bg = t >> 3;

    float a00 = 0.f, a01 = 0.f, a10 = 0.f, a11 = 0.f, a20 = 0.f, a21 = 0.f;

    for (int k0 = 0; k0 < Hdim; k0 += 32) {
        if (t < 192) {
            int r = t >> 3, f4 = t & 7;
            int g = r >> 3, jl = r & 7;
            float4 w = *(const float4*)(W_ih + (size_t)(g * Hdim + j0 + jl) * Hdim + k0 + 4 * f4);
            w_s[r][4 * f4 + 0] = w.x; w_s[r][4 * f4 + 1] = w.y;
            w_s[r][4 * f4 + 2] = w.z; w_s[r][4 * f4 + 3] = w.w;
        }
        #pragma unroll
        for (int i = 0; i < 2; i++) {
            int idx = t + 256 * i;
            int b = idx >> 3, q = idx & 7;
            float4 xv = *(const float4*)(x + (size_t)b * Hdim + k0 + 4 * q);
            x_s[4 * q + 0][b] = xv.x; x_s[4 * q + 1][b] = xv.y;
            x_s[4 * q + 2][b] = xv.z; x_s[4 * q + 3][b] = xv.w;
        }
        __syncthreads();
        #pragma unroll
        for (int kk = 0; kk < 32; kk++) {
            float x0 = x_s[kk][2 * bg], x1 = x_s[kk][2 * bg + 1];
            float w0 = w_s[jj][kk], w1 = w_s[8 + jj][kk], w2 = w_s[16 + jj][kk];
            a00 += w0 * x0; a01 += w0 * x1;
            a10 += w1 * x0; a11 += w1 * x1;
            a20 += w2 * x0; a21 += w2 * x1;
        }
        __syncthreads();
    }

    int j = j0 + jj;
    float bi0 = b_ih[j], bi1 = b_ih[Hdim + j], bi2 = b_ih[2 * Hdim + j];
    float bh0 = b_hh[j], bh1 = b_hh[Hdim + j], bh2 = b_hh[2 * Hdim + j];
    #pragma unroll
    for (int q = 0; q < 2; q++) {
        int b = 2 * bg + q;
        float xr = (q ? a01 : a00) + bi0;
        float xz = (q ? a11 : a10) + bi1;
        float xn = (q ? a21 : a20) + bi2;
        float r = 1.f / (1.f + expf(-(xr + bh0)));
        float z = 1.f / (1.f + expf(-(xz + bh1)));
        float n = tanhf(xn + r * bh2);
        float h = (1.f - z) * n;               // + z*h0, h0 = 0
        g_h[b * Hdim + j] = h;
        g_y[(size_t)b * Ktot + j] = h;
        out_h[b * Hdim + j] = h;
    }
}

// ---------------------------------------------------------------------------
// K2: u[b,e] = sum_h g_h[b,h] * attn_W[h, Hdim+e] — smem-tiled GEMM.
// ---------------------------------------------------------------------------
__global__ __launch_bounds__(256) void u_kernel(const float* __restrict__ attn_W)
{
    __shared__ float Ws[32][20];
    __shared__ float hs[32][65];

    const int t  = threadIdx.x;
    const int e0 = blockIdx.x * 16;
    const int tE = t & 3;
    const int tB = t >> 2;

    float a0 = 0.f, a1 = 0.f, a2 = 0.f, a3 = 0.f;

    for (int k0 = 0; k0 < Hdim; k0 += 32) {
        #pragma unroll
        for (int i = 0; i < 2; i++) {
            int id = t + 256 * i;
            int r = id >> 4, c = id & 15;
            Ws[r][c] = attn_W[(size_t)(k0 + r) * (Hdim + EHdim) + Hdim + e0 + c];
        }
        #pragma unroll
        for (int i = 0; i < 2; i++) {
            int id = t + 256 * i;
            int bb = id >> 3, q = id & 7;
            float4 hv = *(const float4*)(g_h + (size_t)bb * Hdim + k0 + 4 * q);
            hs[4 * q + 0][bb] = hv.x; hs[4 * q + 1][bb] = hv.y;
            hs[4 * q + 2][bb] = hv.z; hs[4 * q + 3][bb] = hv.w;
        }
        __syncthreads();
        #pragma unroll
        for (int kk = 0; kk < 32; kk++) {
            float hv = hs[kk][tB];
            float4 wv = *(const float4*)&Ws[kk][4 * tE];
            a0 += hv * wv.x; a1 += hv * wv.y; a2 += hv * wv.z; a3 += hv * wv.w;
        }
        __syncthreads();
    }
    float* up = g_u + (size_t)tB * EHdim + e0 + 4 * tE;
    up[0] = a0; up[1] = a1; up[2] = a2; up[3] = a3;
}

// ---------------------------------------------------------------------------
// K3a: split-s fused attention, online sub-tiles, 512 THREADS (16 warps).
// Phase A: one dot per warp per sub-tile (2x warps vs R15 for latency hiding).
// Phase B: float2 per thread from the L2-hot 64 KB sub-tile.
// Outputs identical to R15's combine contract.
// ---------------------------------------------------------------------------
__global__ __launch_bounds__(512) void attn_part_kernel(const float* __restrict__ enc)
{
    const int b    = blockIdx.x & 63;          // tile-major launch order
    const int tile = blockIdx.x >> 6;
    const int s0   = tile * TS;
    const int tid  = threadIdx.x;
    const int wid  = tid >> 5, lane = tid & 31;

    __shared__ float sc[SUBS];
    __shared__ float et[SUBS];
    __shared__ float red;

    const float4* uv = (const float4*)(g_u + (size_t)b * EHdim);
    const float*  ebase = enc + (size_t)b * EHdim + 2 * tid;

    float m_run = -FLT_MAX, l_run = 0.f;
    float c0 = 0.f, c1 = 0.f;

    for (int sub = 0; sub < TS / SUBS; sub++) {
        const int sb = s0 + sub * SUBS;

        // ---- phase A: 16 warps x 1 dot ----
        {
            int s = sb + wid;                  // wid in 0..15
            const float4* ev = (const float4*)(enc + (size_t)s * (Bdim * EHdim) + (size_t)b * EHdim);
            float acc = 0.f;
            #pragma unroll 4
            for (int tt = lane; tt < EHdim / 4; tt += 32) {
                float4 e4 = ev[tt], u4 = uv[tt];
                acc += e4.x * u4.x + e4.y * u4.y + e4.z * u4.z + e4.w * u4.w;
            }
            #pragma unroll
            for (int o = 16; o; o >>= 1) acc += __shfl_xor_sync(0xffffffffu, acc, o);
            if (lane == 0) { sc[wid] = acc; g_scores[b * Sdim + s] = acc; }
        }
        __syncthreads();

        // ---- online update (all threads compute identical values) ----
        float m_t = sc[0];
        #pragma unroll
        for (int j = 1; j < SUBS; j++) m_t = fmaxf(m_t, sc[j]);
        float m_new = fmaxf(m_run, m_t);
        float fac = expf(m_run - m_new);       // first sub: exp(-inf)=0

        if (wid == 0) {
            float e = (lane < SUBS) ? expf(sc[lane] - m_new) : 0.f;
            if (lane < SUBS) et[lane] = e;
            #pragma unroll
            for (int o = 16; o; o >>= 1) e += __shfl_xor_sync(0xffffffffu, e, o);
            if (lane == 0) red = e;
        }
        __syncthreads();

        l_run = l_run * fac + red;
        c0 *= fac; c1 *= fac;
        m_run = m_new;

        // ---- phase B: context accumulation, float2/thread, L2-hot ----
        #pragma unroll 4
        for (int j = 0; j < SUBS; j++) {
            float w = et[j];
            float2 e2 = *(const float2*)(ebase + (size_t)(sb + j) * (Bdim * EHdim));
            c0 += w * e2.x; c1 += w * e2.y;
        }
        __syncthreads();                       // sc/et reused next sub-tile
    }

    if (tid == 0) {
        g_mt[b * NTILE + tile] = m_run;
        g_lt[b * NTILE + tile] = l_run;
    }
    float2* pp = (float2*)(g_pctx + (size_t)(b * NTILE + tile) * EHdim + 2 * tid);
    *pp = make_float2(c0, c1);
}

// ---------------------------------------------------------------------------
// K3b: combine partials. Grid = 64 CTAs (per b), 256 threads.
// ---------------------------------------------------------------------------
__global__ __launch_bounds__(256) void attn_combine_kernel(float* __restrict__ out_attn)
{
    const int b   = blockIdx.x;
    const int tid = threadIdx.x;

    __shared__ float fac[NTILE];
    __shared__ float sM, sInv;

    if (tid == 0) {
        float M = -FLT_MAX;
        #pragma unroll
        for (int t = 0; t < NTILE; t++) M = fmaxf(M, g_mt[b * NTILE + t]);
        float L = 0.f;
        #pragma unroll
        for (int t = 0; t < NTILE; t++) {
            float f = expf(g_mt[b * NTILE + t] - M);
            fac[t] = f;
            L += g_lt[b * NTILE + t] * f;
        }
        sM = M; sInv = 1.f / L;
    }
    __syncthreads();
    float M = sM, inv = sInv;

    float c0 = 0.f, c1 = 0.f, c2 = 0.f, c3 = 0.f;
    #pragma unroll
    for (int t = 0; t < NTILE; t++) {
        float f = fac[t];
        const float* pp = g_pctx + (size_t)(b * NTILE + t) * EHdim + 4 * tid;
        c0 += f * pp[0]; c1 += f * pp[1]; c2 += f * pp[2]; c3 += f * pp[3];
    }
    float* yp = g_y + (size_t)b * Ktot + Hdim + 4 * tid;
    yp[0] = c0 * inv; yp[1] = c1 * inv; yp[2] = c2 * inv; yp[3] = c3 * inv;

    #pragma unroll
    for (int i = 0; i < 2; i++) {
        int s = tid + 256 * i;
        float w = expf(g_scores[b * Sdim + s] - M) * inv;
        out_attn[b * Sdim + s] = w;
    }
}

// ---------------------------------------------------------------------------
// K6: dec = y @ out_W^T + out_b via mma.sync tf32 (validated config; at the
// legacy-HMMA MAC-rate floor ~130 MAC/cyc/SM — do not touch).
// ---------------------------------------------------------------------------
#define DEC_M     192
#define DEC_KC    32
#define DEC_KHALF 1024
#define DEC_NCH   (DEC_KHALF / DEC_KC)  // 32 chunks per half
#define RSTR      40
#define AWORDS    (DEC_M * RSTR)        // 7680
#define BWORDS    (Bdim * RSTR)         // 2560
#define BUFWORDS  (AWORDS + BWORDS)     // 10240
#define DEC_SMEM  (2 * BUFWORDS * 4)    // 81920 bytes

template <bool ADD>
__global__ __launch_bounds__(256, 2) void dec_kernel(
    const float* __restrict__ out_W, const float* __restrict__ out_b,
    float* __restrict__ dec, int kbase)
{
    extern __shared__ float smf[];
    const uint32_t sb = smem_to_u32(smf);

    const int tx   = threadIdx.x;
    const int wid  = tx >> 5;
    const int lane = tx & 31;
    const int gid  = lane >> 2;
    const int tig  = lane & 3;
    const int wm   = wid & 3;
    const int wn   = wid >> 2;
    const int rb   = wm * 48;
    const int bb   = wn * 32;
    const int vb   = blockIdx.x * DEC_M;

    float acc[3][4][4];
    #pragma unroll
    for (int mt = 0; mt < 3; mt++)
        #pragma unroll
        for (int nt = 0; nt < 4; nt++)
            #pragma unroll
            for (int i = 0; i < 4; i++) acc[mt][nt][i] = 0.f;

    auto stage = [&](int c, int buf) {
        const int k0 = kbase + c * DEC_KC;
        const uint32_t base = sb + (uint32_t)buf * BUFWORDS * 4;
        #pragma unroll
        for (int i = 0; i < 6; i++) {
            int idx = tx + 256 * i;
            int r = idx >> 3, q = idx & 7;
            int v = vb + r;
            int vc = v < Vdim ? v : (Vdim - 1);
            const float* src = out_W + (size_t)vc * Ktot + k0 + 4 * q;
            uint32_t dst = base + (uint32_t)(r * RSTR + 4 * q) * 4;
            cp_async16_zfill(dst, src, v < Vdim ? 16 : 0);
        }
        #pragma unroll
        for (int i = 0; i < 2; i++) {
            int idx = tx + 256 * i;
            int r = idx >> 3, q = idx & 7;
            const float* src = g_y + (size_t)r * Ktot + k0 + 4 * q;
            uint32_t dst = base + (uint32_t)(AWORDS + r * RSTR + 4 * q) * 4;
            cp_async16(dst, src);
        }
    };

    stage(0, 0);
    CP_COMMIT();

    for (int c = 0; c < DEC_NCH; c++) {
        const int buf = c & 1;
        if (c + 1 < DEC_NCH) {
            stage(c + 1, (c + 1) & 1);
            CP_COMMIT();
            CP_WAIT(1);
        } else {
            CP_WAIT(0);
        }
        __syncthreads();

        const float* As = smf + buf * BUFWORDS;
        const float* Bs = As + AWORDS;
        #pragma unroll
        for (int ks = 0; ks < 4; ks++) {
            const int k = ks * 8;
            uint32_t a[3][4], bf[4][2];
            #pragma unroll
            for (int mt = 0; mt < 3; mt++) {
                int row = rb + mt * 16 + gid;
                uint2 lo = *(const uint2*)(As + row * RSTR + k + 2 * tig);
                uint2 hi = *(const uint2*)(As + (row + 8) * RSTR + k + 2 * tig);
                a[mt][0] = lo.x; a[mt][2] = lo.y;   // logical k = tig, tig+4
                a[mt][1] = hi.x; a[mt][3] = hi.y;
            }
            #pragma unroll
            for (int nt = 0; nt < 4; nt++) {
                int bc2 = bb + nt * 8 + gid;
                uint2 bv = *(const uint2*)(Bs + bc2 * RSTR + k + 2 * tig);
                bf[nt][0] = bv.x; bf[nt][1] = bv.y;
            }
            #pragma unroll
            for (int mt = 0; mt < 3; mt++)
                #pragma unroll
                for (int nt = 0; nt < 4; nt++)
                    mma_tf32(acc[mt][nt], a[mt], bf[nt]);
        }
        __syncthreads();
    }

    #pragma unroll
    for (int mt = 0; mt < 3; mt++) {
        int v0 = vb + rb + mt * 16 + gid;
        int v1 = v0 + 8;
        float bias0 = 0.f, bias1 = 0.f;
        if (!ADD) {
            bias0 = (v0 < Vdim) ? out_b[v0] : 0.f;
            bias1 = (v1 < Vdim) ? out_b[v1] : 0.f;
        }
        #pragma unroll
        for (int nt = 0; nt < 4; nt++) {
            int b0 = bb + nt * 8 + 2 * tig;
            int b1 = b0 + 1;
            if (ADD) {
                if (v0 < Vdim) {
                    dec[(size_t)b0 * Vdim + v0] += acc[mt][nt][0];
                    dec[(size_t)b1 * Vdim + v0] += acc[mt][nt][1];
                }
                if (v1 < Vdim) {
                    dec[(size_t)b0 * Vdim + v1] += acc[mt][nt][2];
                    dec[(size_t)b1 * Vdim + v1] += acc[mt][nt][3];
                }
            } else {
                if (v0 < Vdim) {
                    dec[(size_t)b0 * Vdim + v0] = acc[mt][nt][0] + bias0;
                    dec[(size_t)b1 * Vdim + v0] = acc[mt][nt][1] + bias0;
                }
                if (v1 < Vdim) {
                    dec[(size_t)b0 * Vdim + v1] = acc[mt][nt][2] + bias1;
                    dec[(size_t)b1 * Vdim + v1] = acc[mt][nt][3] + bias1;
                }
            }
        }
    }
}

// ---------------------------------------------------------------------------
// K7a: log_softmax partials. Grid = 64 b x 4 chunks. Online (m, s) per chunk.
// ---------------------------------------------------------------------------
#define LSP_CHUNK ((Vdim + LSP_CH - 1) / LSP_CH)   // 12565
__global__ __launch_bounds__(512) void lsp_kernel(const float* __restrict__ dec)
{
    const int b = blockIdx.x >> 2, c = blockIdx.x & 3;
    const int tid = threadIdx.x;
    const int lo = c * LSP_CHUNK;
    const int hi = min(Vdim, lo + LSP_CHUNK);
    const float* row = dec + (size_t)b * Vdim;

    __shared__ float redM[16], redS[16];

    float m = -FLT_MAX, s = 0.f;
    for (int i = lo + tid; i < hi; i += 512) {
        float x = row[i];
        float mn = fmaxf(m, x);
        s = s * expf(m - mn) + expf(x - mn);
        m = mn;
    }
    #pragma unroll
    for (int o = 16; o; o >>= 1) {
        float m2 = __shfl_xor_sync(0xffffffffu, m, o);
        float s2 = __shfl_xor_sync(0xffffffffu, s, o);
        float mn = fmaxf(m, m2);
        s = s * expf(m - mn) + s2 * expf(m2 - mn);
        m = mn;
    }
    if ((tid & 31) == 0) { redM[tid >> 5] = m; redS[tid >> 5] = s; }
    __syncthreads();
    if (tid < 32) {
        float mm = (tid < 16) ? redM[tid] : -FLT_MAX;
        float ss = (tid < 16) ? redS[tid] : 0.f;
        #pragma unroll
        for (int o = 8; o; o >>= 1) {
            float m2 = __shfl_xor_sync(0xffffffffu, mm, o);
            float s2 = __shfl_xor_sync(0xffffffffu, ss, o);
            float mn = fmaxf(mm, m2);
            ss = ss * expf(mm - mn) + s2 * expf(m2 - mn);
            mm = mn;
        }
        if (tid == 0) { g_lsm[b * LSP_CH + c] = mm; g_lss[b * LSP_CH + c] = ss; }
    }
}

// ---------------------------------------------------------------------------
// K7b: combine lse (deterministic per b) + subtract. Grid = 64 b x 8 segments.
// ---------------------------------------------------------------------------
#define LSP_SEGSZ ((Vdim + LSP_SEG - 1) / LSP_SEG)   // 6283
__global__ __launch_bounds__(512) void lsub_kernel(float* __restrict__ dec)
{
    const int b = blockIdx.x >> 3, seg = blockIdx.x & 7;
    const int tid = threadIdx.x;

    float M = -FLT_MAX;
    #pragma unroll
    for (int c = 0; c < LSP_CH; c++) M = fmaxf(M, g_lsm[b * LSP_CH + c]);
    float S = 0.f;
    #pragma unroll
    for (int c = 0; c < LSP_CH; c++) S += g_lss[b * LSP_CH + c] * expf(g_lsm[b * LSP_CH + c] - M);
    float lse = M + logf(S);

    const int lo = seg * LSP_SEGSZ;
    const int hi = min(Vdim, lo + LSP_SEGSZ);
    float* row = dec + (size_t)b * Vdim;
    for (int i = lo + tid; i < hi; i += 512) row[i] -= lse;
}

// ---------------------------------------------------------------------------
extern "C" void kernel_launch(void* const* d_in, const int* in_sizes, int n_in,
                              void* d_out, int out_size)
{
    const float* x      = (const float*)d_in[0];
    const float* enc    = (const float*)d_in[1];
    const float* W_ih   = (const float*)d_in[3];
    const float* b_ih   = (const float*)d_in[5];
    const float* b_hh   = (const float*)d_in[6];
    const float* attn_W = (const float*)d_in[7];
    const float* out_W  = (const float*)d_in[9];
    const float* out_b  = (const float*)d_in[10];

    float* out = (float*)d_out;
    const size_t OFF_H    = (size_t)Bdim * Vdim;
    const size_t OFF_ATTN = OFF_H + (size_t)Bdim * Hdim;
    const int DEC_GRID = (Vdim + DEC_M - 1) / DEC_M;   // 262

    cudaFuncSetAttribute(dec_kernel<false>, cudaFuncAttributeMaxDynamicSharedMemorySize, DEC_SMEM);
    cudaFuncSetAttribute(dec_kernel<true>,  cudaFuncAttributeMaxDynamicSharedMemorySize, DEC_SMEM);

    // Fork: dec's h-half (K 0..1024) depends only on gru; runs on a side
    // stream while the attention chain proceeds on the main stream.
    cudaStream_t s2;
    cudaEvent_t ev_gru, ev_dech;
    cudaStreamCreateWithFlags(&s2, cudaStreamNonBlocking);
    cudaEventCreateWithFlags(&ev_gru,  cudaEventDisableTiming);
    cudaEventCreateWithFlags(&ev_dech, cudaEventDisableTiming);

    gru_kernel<<<128, 256>>>(x, W_ih, b_ih, b_hh, out + OFF_H);
    cudaEventRecord(ev_gru, 0);
    cudaStreamWaitEvent(s2, ev_gru, 0);
    dec_kernel<false><<<DEC_GRID, 256, DEC_SMEM, s2>>>(out_W, out_b, out, 0);
    cudaEventRecord(ev_dech, s2);

    u_kernel<<<64, 256>>>(attn_W);
    attn_part_kernel<<<Bdim * NTILE, 512>>>(enc);
    attn_combine_kernel<<<Bdim, 256>>>(out + OFF_ATTN);

    cudaStreamWaitEvent(0, ev_dech, 0);   // join fork before the += half
    dec_kernel<true><<<DEC_GRID, 256, DEC_SMEM>>>(out_W, out_b, out, 1024);
    lsp_kernel<<<Bdim * LSP_CH, 512>>>(out);
    lsub_kernel<<<Bdim * LSP_SEG, 512>>>(out);
}

// round 17
// speedup vs baseline: 1.0242x; 1.0242x over previous
#include <cuda_runtime.h>
#include <cstdint>
#include <cfloat>

#define Sdim 512
#define Bdim 64
#define Hdim 1024
#define EHdim 1024
#define Vdim 50257
#define Ktot 2048              // H + EH
#define NTILE 8                // s-tiles per b
#define TS    64               // s per tile
#define SUBS  16               // s per online sub-tile
#define LSP_CH 4               // logsoftmax partial chunks per row
#define LSP_SEG 8              // subtract segments per row

// ---- scratch (no allocations allowed) ----
__device__ float g_h[Bdim * Hdim];
__device__ float g_u[Bdim * EHdim];
__device__ float g_scores[Bdim * Sdim];
__device__ float g_mt[Bdim * NTILE];
__device__ float g_lt[Bdim * NTILE];
__device__ float g_pctx[Bdim * NTILE * EHdim];   // 2 MB partial contexts
__device__ float g_y[Bdim * Ktot];   // [h | context], K-major per b
__device__ float g_lsm[Bdim * LSP_CH];
__device__ float g_lss[Bdim * LSP_CH];

// ============================================================================
// sm_80-class PTX helpers (safe under .target sm_103 — no 'a' features)
// ============================================================================
__device__ __forceinline__ uint32_t smem_to_u32(const void* p) {
    uint32_t a;
    asm("{ .reg .u64 t; cvta.to.shared.u64 t, %1; cvt.u32.u64 %0, t; }" : "=r"(a) : "l"(p));
    return a;
}
__device__ __forceinline__ void cp_async16(uint32_t dst, const void* src) {
    asm volatile("cp.async.ca.shared.global [%0], [%1], 16;" :: "r"(dst), "l"(src));
}
__device__ __forceinline__ void cp_async16_zfill(uint32_t dst, const void* src, int src_bytes) {
    asm volatile("cp.async.ca.shared.global [%0], [%1], 16, %2;"
                 :: "r"(dst), "l"(src), "r"(src_bytes));
}
#define CP_COMMIT() asm volatile("cp.async.commit_group;" ::: "memory")
#define CP_WAIT(n)  asm volatile("cp.async.wait_group %0;" :: "n"(n) : "memory")

__device__ __forceinline__ void mma_tf32(float* c, const uint32_t* a, const uint32_t* b) {
    asm volatile("mma.sync.aligned.m16n8k8.row.col.f32.tf32.tf32.f32 "
        "{%0,%1,%2,%3}, {%4,%5,%6,%7}, {%8,%9}, {%0,%1,%2,%3};"
        : "+f"(c[0]), "+f"(c[1]), "+f"(c[2]), "+f"(c[3])
        : "r"(a[0]), "r"(a[1]), "r"(a[2]), "r"(a[3]), "r"(b[0]), "r"(b[1]));
}

// ---------------------------------------------------------------------------
// K1: GRU with h0=0 => gh = b_hh. Tiled GEMM: block = 8 j x 64 b, K via smem.
// ---------------------------------------------------------------------------
__global__ __launch_bounds__(256) void gru_kernel(
    const float* __restrict__ x, const float* __restrict__ W_ih,
    const float* __restrict__ b_ih, const float* __restrict__ b_hh,
    float* __restrict__ out_h)
{
    __shared__ float w_s[24][33];
    __shared__ float x_s[32][65];

    const int t  = threadIdx.x;
    const int j0 = blockIdx.x * 8;
    const int jj = t & 7;
    const int bg = t >> 3;

    float a00 = 0.f, a01 = 0.f, a10 = 0.f, a11 = 0.f, a20 = 0.f, a21 = 0.f;

    for (int k0 = 0; k0 < Hdim; k0 += 32) {
        if (t < 192) {
            int r = t >> 3, f4 = t & 7;
            int g = r >> 3, jl = r & 7;
            float4 w = *(const float4*)(W_ih + (size_t)(g * Hdim + j0 + jl) * Hdim + k0 + 4 * f4);
            w_s[r][4 * f4 + 0] = w.x; w_s[r][4 * f4 + 1] = w.y;
            w_s[r][4 * f4 + 2] = w.z; w_s[r][4 * f4 + 3] = w.w;
        }
        #pragma unroll
        for (int i = 0; i < 2; i++) {
            int idx = t + 256 * i;
            int b = idx >> 3, q = idx & 7;
            float4 xv = *(const float4*)(x + (size_t)b * Hdim + k0 + 4 * q);
            x_s[4 * q + 0][b] = xv.x; x_s[4 * q + 1][b] = xv.y;
            x_s[4 * q + 2][b] = xv.z; x_s[4 * q + 3][b] = xv.w;
        }
        __syncthreads();
        #pragma unroll
        for (int kk = 0; kk < 32; kk++) {
            float x0 = x_s[kk][2 * bg], x1 = x_s[kk][2 * bg + 1];
            float w0 = w_s[jj][kk], w1 = w_s[8 + jj][kk], w2 = w_s[16 + jj][kk];
            a00 += w0 * x0; a01 += w0 * x1;
            a10 += w1 * x0; a11 += w1 * x1;
            a20 += w2 * x0; a21 += w2 * x1;
        }
        __syncthreads();
    }

    int j = j0 + jj;
    float bi0 = b_ih[j], bi1 = b_ih[Hdim + j], bi2 = b_ih[2 * Hdim + j];
    float bh0 = b_hh[j], bh1 = b_hh[Hdim + j], bh2 = b_hh[2 * Hdim + j];
    #pragma unroll
    for (int q = 0; q < 2; q++) {
        int b = 2 * bg + q;
        float xr = (q ? a01 : a00) + bi0;
        float xz = (q ? a11 : a10) + bi1;
        float xn = (q ? a21 : a20) + bi2;
        float r = 1.f / (1.f + expf(-(xr + bh0)));
        float z = 1.f / (1.f + expf(-(xz + bh1)));
        float n = tanhf(xn + r * bh2);
        float h = (1.f - z) * n;               // + z*h0, h0 = 0
        g_h[b * Hdim + j] = h;
        g_y[(size_t)b * Ktot + j] = h;
        out_h[b * Hdim + j] = h;
    }
}

// ---------------------------------------------------------------------------
// K2: u[b,e] = sum_h g_h[b,h] * attn_W[h, Hdim+e] — smem-tiled GEMM.
// ---------------------------------------------------------------------------
__global__ __launch_bounds__(256) void u_kernel(const float* __restrict__ attn_W)
{
    __shared__ float Ws[32][20];
    __shared__ float hs[32][65];

    const int t  = threadIdx.x;
    const int e0 = blockIdx.x * 16;
    const int tE = t & 3;
    const int tB = t >> 2;

    float a0 = 0.f, a1 = 0.f, a2 = 0.f, a3 = 0.f;

    for (int k0 = 0; k0 < Hdim; k0 += 32) {
        #pragma unroll
        for (int i = 0; i < 2; i++) {
            int id = t + 256 * i;
            int r = id >> 4, c = id & 15;
            Ws[r][c] = attn_W[(size_t)(k0 + r) * (Hdim + EHdim) + Hdim + e0 + c];
        }
        #pragma unroll
        for (int i = 0; i < 2; i++) {
            int id = t + 256 * i;
            int bb = id >> 3, q = id & 7;
            float4 hv = *(const float4*)(g_h + (size_t)bb * Hdim + k0 + 4 * q);
            hs[4 * q + 0][bb] = hv.x; hs[4 * q + 1][bb] = hv.y;
            hs[4 * q + 2][bb] = hv.z; hs[4 * q + 3][bb] = hv.w;
        }
        __syncthreads();
        #pragma unroll
        for (int kk = 0; kk < 32; kk++) {
            float hv = hs[kk][tB];
            float4 wv = *(const float4*)&Ws[kk][4 * tE];
            a0 += hv * wv.x; a1 += hv * wv.y; a2 += hv * wv.z; a3 += hv * wv.w;
        }
        __syncthreads();
    }
    float* up = g_u + (size_t)tB * EHdim + e0 + 4 * tE;
    up[0] = a0; up[1] = a1; up[2] = a2; up[3] = a3;
}

// ---------------------------------------------------------------------------
// K3a: split-s fused attention, online sub-tiles (R15-validated: 256 threads,
// 8 warps x 2 dots phase A, float4/thread phase B — 34.0 us @ 51% DRAM).
// ---------------------------------------------------------------------------
__global__ __launch_bounds__(256) void attn_part_kernel(const float* __restrict__ enc)
{
    const int b    = blockIdx.x & 63;          // tile-major launch order
    const int tile = blockIdx.x >> 6;
    const int s0   = tile * TS;
    const int tid  = threadIdx.x;
    const int wid  = tid >> 5, lane = tid & 31;

    __shared__ float sc[SUBS];
    __shared__ float et[SUBS];
    __shared__ float red;

    const float4* uv = (const float4*)(g_u + (size_t)b * EHdim);
    const float*  ebase = enc + (size_t)b * EHdim + 4 * tid;

    float m_run = -FLT_MAX, l_run = 0.f;
    float c0 = 0.f, c1 = 0.f, c2 = 0.f, c3 = 0.f;

    for (int sub = 0; sub < TS / SUBS; sub++) {
        const int sb = s0 + sub * SUBS;

        // ---- phase A: 8 warps x 2 dots ----
        #pragma unroll
        for (int i = 0; i < 2; i++) {
            int sl = wid * 2 + i;              // 0..15
            int s = sb + sl;
            const float4* ev = (const float4*)(enc + (size_t)s * (Bdim * EHdim) + (size_t)b * EHdim);
            float acc = 0.f;
            #pragma unroll 4
            for (int tt = lane; tt < EHdim / 4; tt += 32) {
                float4 e4 = ev[tt], u4 = uv[tt];
                acc += e4.x * u4.x + e4.y * u4.y + e4.z * u4.z + e4.w * u4.w;
            }
            #pragma unroll
            for (int o = 16; o; o >>= 1) acc += __shfl_xor_sync(0xffffffffu, acc, o);
            if (lane == 0) { sc[sl] = acc; g_scores[b * Sdim + s] = acc; }
        }
        __syncthreads();

        // ---- online update: every thread computes identical m_t/m_new/fac ----
        float m_t = sc[0];
        #pragma unroll
        for (int j = 1; j < SUBS; j++) m_t = fmaxf(m_t, sc[j]);
        float m_new = fmaxf(m_run, m_t);
        float fac = expf(m_run - m_new);       // first sub: exp(-inf)=0

        // warp 0 computes exps + sub-sum
        if (wid == 0) {
            float e = (lane < SUBS) ? expf(sc[lane] - m_new) : 0.f;
            if (lane < SUBS) et[lane] = e;
            #pragma unroll
            for (int o = 16; o; o >>= 1) e += __shfl_xor_sync(0xffffffffu, e, o);
            if (lane == 0) red = e;
        }
        __syncthreads();

        l_run = l_run * fac + red;
        c0 *= fac; c1 *= fac; c2 *= fac; c3 *= fac;
        m_run = m_new;

        // ---- phase B: context accumulation from L2-hot sub-tile ----
        #pragma unroll 4
        for (int j = 0; j < SUBS; j++) {
            float w = et[j];
            float4 e4 = *(const float4*)(ebase + (size_t)(sb + j) * (Bdim * EHdim));
            c0 += w * e4.x; c1 += w * e4.y; c2 += w * e4.z; c3 += w * e4.w;
        }
        __syncthreads();                       // sc/et reused next sub-tile
    }

    if (tid == 0) {
        g_mt[b * NTILE + tile] = m_run;
        g_lt[b * NTILE + tile] = l_run;
    }
    float* pp = g_pctx + (size_t)(b * NTILE + tile) * EHdim + 4 * tid;
    pp[0] = c0; pp[1] = c1; pp[2] = c2; pp[3] = c3;
}

// ---------------------------------------------------------------------------
// K3b: combine partials. Grid = 64 CTAs (per b), 256 threads.
// ---------------------------------------------------------------------------
__global__ __launch_bounds__(256) void attn_combine_kernel(float* __restrict__ out_attn)
{
    const int b   = blockIdx.x;
    const int tid = threadIdx.x;

    __shared__ float fac[NTILE];
    __shared__ float sM, sInv;

    if (tid == 0) {
        float M = -FLT_MAX;
        #pragma unroll
        for (int t = 0; t < NTILE; t++) M = fmaxf(M, g_mt[b * NTILE + t]);
        float L = 0.f;
        #pragma unroll
        for (int t = 0; t < NTILE; t++) {
            float f = expf(g_mt[b * NTILE + t] - M);
            fac[t] = f;
            L += g_lt[b * NTILE + t] * f;
        }
        sM = M; sInv = 1.f / L;
    }
    __syncthreads();
    float M = sM, inv = sInv;

    float c0 = 0.f, c1 = 0.f, c2 = 0.f, c3 = 0.f;
    #pragma unroll
    for (int t = 0; t < NTILE; t++) {
        float f = fac[t];
        const float* pp = g_pctx + (size_t)(b * NTILE + t) * EHdim + 4 * tid;
        c0 += f * pp[0]; c1 += f * pp[1]; c2 += f * pp[2]; c3 += f * pp[3];
    }
    float* yp = g_y + (size_t)b * Ktot + Hdim + 4 * tid;
    yp[0] = c0 * inv; yp[1] = c1 * inv; yp[2] = c2 * inv; yp[3] = c3 * inv;

    #pragma unroll
    for (int i = 0; i < 2; i++) {
        int s = tid + 256 * i;
        float w = expf(g_scores[b * Sdim + s] - M) * inv;
        out_attn[b * Sdim + s] = w;
    }
}

// ---------------------------------------------------------------------------
// K6: dec = y @ out_W^T + out_b via mma.sync tf32 (validated config; at the
// legacy-HMMA MAC-rate floor ~130 MAC/cyc/SM — do not touch).
// ---------------------------------------------------------------------------
#define DEC_M     192
#define DEC_KC    32
#define DEC_KHALF 1024
#define DEC_NCH   (DEC_KHALF / DEC_KC)  // 32 chunks per half
#define RSTR      40
#define AWORDS    (DEC_M * RSTR)        // 7680
#define BWORDS    (Bdim * RSTR)         // 2560
#define BUFWORDS  (AWORDS + BWORDS)     // 10240
#define DEC_SMEM  (2 * BUFWORDS * 4)    // 81920 bytes

template <bool ADD>
__global__ __launch_bounds__(256, 2) void dec_kernel(
    const float* __restrict__ out_W, const float* __restrict__ out_b,
    float* __restrict__ dec, int kbase)
{
    extern __shared__ float smf[];
    const uint32_t sb = smem_to_u32(smf);

    const int tx   = threadIdx.x;
    const int wid  = tx >> 5;
    const int lane = tx & 31;
    const int gid  = lane >> 2;
    const int tig  = lane & 3;
    const int wm   = wid & 3;
    const int wn   = wid >> 2;
    const int rb   = wm * 48;
    const int bb   = wn * 32;
    const int vb   = blockIdx.x * DEC_M;

    float acc[3][4][4];
    #pragma unroll
    for (int mt = 0; mt < 3; mt++)
        #pragma unroll
        for (int nt = 0; nt < 4; nt++)
            #pragma unroll
            for (int i = 0; i < 4; i++) acc[mt][nt][i] = 0.f;

    auto stage = [&](int c, int buf) {
        const int k0 = kbase + c * DEC_KC;
        const uint32_t base = sb + (uint32_t)buf * BUFWORDS * 4;
        #pragma unroll
        for (int i = 0; i < 6; i++) {
            int idx = tx + 256 * i;
            int r = idx >> 3, q = idx & 7;
            int v = vb + r;
            int vc = v < Vdim ? v : (Vdim - 1);
            const float* src = out_W + (size_t)vc * Ktot + k0 + 4 * q;
            uint32_t dst = base + (uint32_t)(r * RSTR + 4 * q) * 4;
            cp_async16_zfill(dst, src, v < Vdim ? 16 : 0);
        }
        #pragma unroll
        for (int i = 0; i < 2; i++) {
            int idx = tx + 256 * i;
            int r = idx >> 3, q = idx & 7;
            const float* src = g_y + (size_t)r * Ktot + k0 + 4 * q;
            uint32_t dst = base + (uint32_t)(AWORDS + r * RSTR + 4 * q) * 4;
            cp_async16(dst, src);
        }
    };

    stage(0, 0);
    CP_COMMIT();

    for (int c = 0; c < DEC_NCH; c++) {
        const int buf = c & 1;
        if (c + 1 < DEC_NCH) {
            stage(c + 1, (c + 1) & 1);
            CP_COMMIT();
            CP_WAIT(1);
        } else {
            CP_WAIT(0);
        }
        __syncthreads();

        const float* As = smf + buf * BUFWORDS;
        const float* Bs = As + AWORDS;
        #pragma unroll
        for (int ks = 0; ks < 4; ks++) {
            const int k = ks * 8;
            uint32_t a[3][4], bf[4][2];
            #pragma unroll
            for (int mt = 0; mt < 3; mt++) {
                int row = rb + mt * 16 + gid;
                uint2 lo = *(const uint2*)(As + row * RSTR + k + 2 * tig);
                uint2 hi = *(const uint2*)(As + (row + 8) * RSTR + k + 2 * tig);
                a[mt][0] = lo.x; a[mt][2] = lo.y;   // logical k = tig, tig+4
                a[mt][1] = hi.x; a[mt][3] = hi.y;
            }
            #pragma unroll
            for (int nt = 0; nt < 4; nt++) {
                int bc2 = bb + nt * 8 + gid;
                uint2 bv = *(const uint2*)(Bs + bc2 * RSTR + k + 2 * tig);
                bf[nt][0] = bv.x; bf[nt][1] = bv.y;
            }
            #pragma unroll
            for (int mt = 0; mt < 3; mt++)
                #pragma unroll
                for (int nt = 0; nt < 4; nt++)
                    mma_tf32(acc[mt][nt], a[mt], bf[nt]);
        }
        __syncthreads();
    }

    #pragma unroll
    for (int mt = 0; mt < 3; mt++) {
        int v0 = vb + rb + mt * 16 + gid;
        int v1 = v0 + 8;
        float bias0 = 0.f, bias1 = 0.f;
        if (!ADD) {
            bias0 = (v0 < Vdim) ? out_b[v0] : 0.f;
            bias1 = (v1 < Vdim) ? out_b[v1] : 0.f;
        }
        #pragma unroll
        for (int nt = 0; nt < 4; nt++) {
            int b0 = bb + nt * 8 + 2 * tig;
            int b1 = b0 + 1;
            if (ADD) {
                if (v0 < Vdim) {
                    dec[(size_t)b0 * Vdim + v0] += acc[mt][nt][0];
                    dec[(size_t)b1 * Vdim + v0] += acc[mt][nt][1];
                }
                if (v1 < Vdim) {
                    dec[(size_t)b0 * Vdim + v1] += acc[mt][nt][2];
                    dec[(size_t)b1 * Vdim + v1] += acc[mt][nt][3];
                }
            } else {
                if (v0 < Vdim) {
                    dec[(size_t)b0 * Vdim + v0] = acc[mt][nt][0] + bias0;
                    dec[(size_t)b1 * Vdim + v0] = acc[mt][nt][1] + bias0;
                }
                if (v1 < Vdim) {
                    dec[(size_t)b0 * Vdim + v1] = acc[mt][nt][2] + bias1;
                    dec[(size_t)b1 * Vdim + v1] = acc[mt][nt][3] + bias1;
                }
            }
        }
    }
}

// ---------------------------------------------------------------------------
// K7a: log_softmax partials. Grid = 64 b x 4 chunks. Online (m, s) per chunk.
// ---------------------------------------------------------------------------
#define LSP_CHUNK ((Vdim + LSP_CH - 1) / LSP_CH)   // 12565
__global__ __launch_bounds__(512) void lsp_kernel(const float* __restrict__ dec)
{
    const int b = blockIdx.x >> 2, c = blockIdx.x & 3;
    const int tid = threadIdx.x;
    const int lo = c * LSP_CHUNK;
    const int hi = min(Vdim, lo + LSP_CHUNK);
    const float* row = dec + (size_t)b * Vdim;

    __shared__ float redM[16], redS[16];

    float m = -FLT_MAX, s = 0.f;
    for (int i = lo + tid; i < hi; i += 512) {
        float x = row[i];
        float mn = fmaxf(m, x);
        s = s * expf(m - mn) + expf(x - mn);
        m = mn;
    }
    #pragma unroll
    for (int o = 16; o; o >>= 1) {
        float m2 = __shfl_xor_sync(0xffffffffu, m, o);
        float s2 = __shfl_xor_sync(0xffffffffu, s, o);
        float mn = fmaxf(m, m2);
        s = s * expf(m - mn) + s2 * expf(m2 - mn);
        m = mn;
    }
    if ((tid & 31) == 0) { redM[tid >> 5] = m; redS[tid >> 5] = s; }
    __syncthreads();
    if (tid < 32) {
        float mm = (tid < 16) ? redM[tid] : -FLT_MAX;
        float ss = (tid < 16) ? redS[tid] : 0.f;
        #pragma unroll
        for (int o = 8; o; o >>= 1) {
            float m2 = __shfl_xor_sync(0xffffffffu, mm, o);
            float s2 = __shfl_xor_sync(0xffffffffu, ss, o);
            float mn = fmaxf(mm, m2);
            ss = ss * expf(mm - mn) + s2 * expf(m2 - mn);
            mm = mn;
        }
        if (tid == 0) { g_lsm[b * LSP_CH + c] = mm; g_lss[b * LSP_CH + c] = ss; }
    }
}

// ---------------------------------------------------------------------------
// K7b: combine lse (deterministic per b) + subtract. Grid = 64 b x 8 segments.
// ---------------------------------------------------------------------------
#define LSP_SEGSZ ((Vdim + LSP_SEG - 1) / LSP_SEG)   // 6283
__global__ __launch_bounds__(512) void lsub_kernel(float* __restrict__ dec)
{
    const int b = blockIdx.x >> 3, seg = blockIdx.x & 7;
    const int tid = threadIdx.x;

    float M = -FLT_MAX;
    #pragma unroll
    for (int c = 0; c < LSP_CH; c++) M = fmaxf(M, g_lsm[b * LSP_CH + c]);
    float S = 0.f;
    #pragma unroll
    for (int c = 0; c < LSP_CH; c++) S += g_lss[b * LSP_CH + c] * expf(g_lsm[b * LSP_CH + c] - M);
    float lse = M + logf(S);

    const int lo = seg * LSP_SEGSZ;
    const int hi = min(Vdim, lo + LSP_SEGSZ);
    float* row = dec + (size_t)b * Vdim;
    for (int i = lo + tid; i < hi; i += 512) row[i] -= lse;
}

// ---------------------------------------------------------------------------
extern "C" void kernel_launch(void* const* d_in, const int* in_sizes, int n_in,
                              void* d_out, int out_size)
{
    const float* x      = (const float*)d_in[0];
    const float* enc    = (const float*)d_in[1];
    const float* W_ih   = (const float*)d_in[3];
    const float* b_ih   = (const float*)d_in[5];
    const float* b_hh   = (const float*)d_in[6];
    const float* attn_W = (const float*)d_in[7];
    const float* out_W  = (const float*)d_in[9];
    const float* out_b  = (const float*)d_in[10];

    float* out = (float*)d_out;
    const size_t OFF_H    = (size_t)Bdim * Vdim;
    const size_t OFF_ATTN = OFF_H + (size_t)Bdim * Hdim;
    const int DEC_GRID = (Vdim + DEC_M - 1) / DEC_M;   // 262

    cudaFuncSetAttribute(dec_kernel<false>, cudaFuncAttributeMaxDynamicSharedMemorySize, DEC_SMEM);
    cudaFuncSetAttribute(dec_kernel<true>,  cudaFuncAttributeMaxDynamicSharedMemorySize, DEC_SMEM);

    // Fork: dec's h-half (K 0..1024) depends only on gru; runs on a side
    // stream while the attention chain proceeds on the main stream.
    cudaStream_t s2;
    cudaEvent_t ev_gru, ev_dech;
    cudaStreamCreateWithFlags(&s2, cudaStreamNonBlocking);
    cudaEventCreateWithFlags(&ev_gru,  cudaEventDisableTiming);
    cudaEventCreateWithFlags(&ev_dech, cudaEventDisableTiming);

    gru_kernel<<<128, 256>>>(x, W_ih, b_ih, b_hh, out + OFF_H);
    cudaEventRecord(ev_gru, 0);
    cudaStreamWaitEvent(s2, ev_gru, 0);
    dec_kernel<false><<<DEC_GRID, 256, DEC_SMEM, s2>>>(out_W, out_b, out, 0);
    cudaEventRecord(ev_dech, s2);

    u_kernel<<<64, 256>>>(attn_W);
    attn_part_kernel<<<Bdim * NTILE, 256>>>(enc);
    attn_combine_kernel<<<Bdim, 256>>>(out + OFF_ATTN);

    cudaStreamWaitEvent(0, ev_dech, 0);   // join fork before the += half
    dec_kernel<true><<<DEC_GRID, 256, DEC_SMEM>>>(out_W, out_b, out, 1024);
    lsp_kernel<<<Bdim * LSP_CH, 512>>>(out);
    lsub_kernel<<<Bdim * LSP_SEG, 512>>>(out);
}